// round 1
// baseline (speedup 1.0000x reference)
#include <cuda_runtime.h>

// ---------------------------------------------------------------------------
// FLD fused forward, fp32 baseline with algebraic folding:
//   - W_k folded against batch-invariant q  -> 24-wide score projection
//   - key never materialized (affine in t + 64 sin terms)
//   - "ones" half of attention output folded into b_o_eff
//   - layer-1 GEMM folded through the polynomial in t (d0,d1,d2 per batch)
//   - kF: fused h1 -> h2=relu(@W2+b2) -> out=@W3+b3, smem-tiled SGEMM
// ---------------------------------------------------------------------------

#define Bb   64
#define Lq   2048
#define Tt   1024
#define Dd   128
#define Ee   512
#define NH   8
#define Pp   3
#define HP   24          // NH * Pp
#define LAT  256
#define HID  512

// scratch (static device allocations; no runtime alloc)
__device__ float g_q[Pp * Ee];            // q[p][e]
__device__ float g_A[Ee * HP];            // A[e][hp], hp = h*3+p, includes /8
__device__ float g_Clin[HP];
__device__ float g_Cconst[HP];
__device__ float g_boeff[LAT];
__device__ float g_scores[Bb * HP * Lq];  // [b][hp][l]
__device__ float g_rowmax[Bb * HP];
__device__ float g_pnum[Bb * 8 * HP * Dd];
__device__ float g_pden[Bb * 8 * HP * Dd];
__device__ float g_d[Bb * 3 * HID];       // d0,d1,d2 per batch

// ---------------- kA1: q[p][e] = query[p] @ W_q + b_q  (grid=3, block=512)
__global__ void kA1(const float* __restrict__ query,
                    const float* __restrict__ W_q,
                    const float* __restrict__ b_q) {
    int p = blockIdx.x;
    int e = threadIdx.x;
    float acc = b_q[e];
    for (int e2 = 0; e2 < Ee; e2++)
        acc = fmaf(query[p * Ee + e2], W_q[e2 * Ee + e], acc);
    g_q[p * Ee + e] = acc;
}

// ---------------- kA2: A[e][hp] = (1/8) sum_j W_k[e][h*64+j] * q[p][h*64+j]
// grid=64 blocks (8 e-rows each), block=256
__global__ void kA2(const float* __restrict__ W_k) {
    __shared__ float wk[8 * Ee];     // 16KB
    int tid = threadIdx.x;
    int e0 = blockIdx.x * 8;
    for (int i = tid; i < 8 * Ee / 4; i += 256)
        *(float4*)&wk[i * 4] = *(const float4*)&W_k[e0 * Ee + i * 4];
    __syncthreads();
    if (tid < 8 * HP) {
        int el = tid / HP;
        int hp = tid % HP;
        int h = hp / 3, p = hp % 3;
        const float* wr = &wk[el * Ee + h * 64];
        const float* qr = &g_q[p * Ee + h * 64];
        float acc = 0.f;
        #pragma unroll 8
        for (int j = 0; j < 64; j++)
            acc = fmaf(wr[j], qr[j], acc);
        g_A[(e0 + el) * HP + hp] = acc * 0.125f;
    }
}

// ---------------- kA3: C_lin, C_const (incl. bias from b_k), b_o_eff
// 1 block, 256 threads
__global__ void kA3(const float* __restrict__ w_te,
                    const float* __restrict__ b_te,
                    const float* __restrict__ b_k,
                    const float* __restrict__ W_o,
                    const float* __restrict__ b_o) {
    int tid = threadIdx.x;
    if (tid < HP) {
        int hp = tid;
        int h = hp / 3, p = hp % 3;
        float bias = 0.f;
        for (int j = 0; j < 64; j++)
            bias = fmaf(b_k[h * 64 + j], g_q[p * Ee + h * 64 + j], bias);
        bias *= 0.125f;
        float cl = 0.f, cc = 0.f;
        for (int e = 0; e < Ee; e++) {
            if ((e & 7) == 0) continue;   // sin positions handled separately
            float a = g_A[e * HP + hp];
            cl = fmaf(w_te[e], a, cl);
            cc = fmaf(b_te[e], a, cc);
        }
        g_Clin[hp] = cl;
        g_Cconst[hp] = cc + bias;
    }
    // b_o_eff[o] = b_o[o] + sum over "ones" rows of W_o
    {
        int o = tid;   // 256 threads == LAT
        float acc = b_o[o];
        for (int h = 0; h < NH; h++)
            for (int c = 0; c < Dd; c++)
                acc += W_o[(h * 2 * Dd + Dd + c) * LAT + o];
        g_boeff[o] = acc;
    }
}

// ---------------- kB: scores[b][hp][l]   grid=512, block=256 (token/thread)
__global__ void kB(const float* __restrict__ timesteps,
                   const float* __restrict__ w_te,
                   const float* __restrict__ b_te) {
    __shared__ float sAs[64 * HP];
    __shared__ float sw[64], sb[64], sCl[HP], sCc[HP];
    int tid = threadIdx.x;
    for (int i = tid; i < 64 * HP; i += 256) {
        int j = i / HP, hp = i % HP;
        sAs[i] = g_A[(j * 8) * HP + hp];
    }
    if (tid < 64) { sw[tid] = w_te[tid * 8]; sb[tid] = b_te[tid * 8]; }
    if (tid < HP) { sCl[tid] = g_Clin[tid]; sCc[tid] = g_Cconst[tid]; }
    __syncthreads();

    int idx = blockIdx.x * 256 + tid;           // b*Lq + l
    float t = timesteps[idx];
    float acc[HP];
    #pragma unroll
    for (int hp = 0; hp < HP; hp++) acc[hp] = fmaf(t, sCl[hp], sCc[hp]);
    for (int j = 0; j < 64; j++) {
        float sv = sinf(fmaf(t, sw[j], sb[j]));
        #pragma unroll
        for (int hp = 0; hp < HP; hp++)
            acc[hp] = fmaf(sv, sAs[j * HP + hp], acc[hp]);
    }
    int b = idx >> 11, l = idx & 2047;
    #pragma unroll
    for (int hp = 0; hp < HP; hp++)
        g_scores[(b * HP + hp) * Lq + l] = acc[hp];
}

// ---------------- kC: row max over L   grid=B*HP, block=128
__global__ void kC() {
    int row = blockIdx.x;
    int tid = threadIdx.x;
    const float* s = &g_scores[row * Lq];
    float m = -1e30f;
    for (int l = tid; l < Lq; l += 128) m = fmaxf(m, s[l]);
    #pragma unroll
    for (int o = 16; o > 0; o >>= 1)
        m = fmaxf(m, __shfl_xor_sync(0xffffffffu, m, o));
    __shared__ float sm4[4];
    if ((tid & 31) == 0) sm4[tid >> 5] = m;
    __syncthreads();
    if (tid == 0)
        g_rowmax[row] = fmaxf(fmaxf(sm4[0], sm4[1]), fmaxf(sm4[2], sm4[3]));
}

// ---------------- kD: partial weighted sums   grid=(B,8), block=128 (c/thread)
__global__ void kD(const float* __restrict__ X,
                   const float* __restrict__ M) {
    __shared__ float wbuf[HP * 256];
    __shared__ float srm[HP];
    int b = blockIdx.x, ch = blockIdx.y;
    int tid = threadIdx.x;
    if (tid < HP) srm[tid] = g_rowmax[b * HP + tid];
    __syncthreads();
    for (int i = tid; i < HP * 256; i += 128) {
        int hp = i >> 8, l0 = i & 255;
        wbuf[i] = expf(g_scores[(b * HP + hp) * Lq + ch * 256 + l0] - srm[hp]);
    }
    __syncthreads();

    float an[HP], ad[HP];
    #pragma unroll
    for (int hp = 0; hp < HP; hp++) { an[hp] = 0.f; ad[hp] = 0.f; }
    int c = tid;
    const float* Xb = X + ((long)b * Lq + ch * 256) * Dd + c;
    const float* Mb = M + ((long)b * Lq + ch * 256) * Dd + c;
    for (int l0 = 0; l0 < 256; l0++) {
        float xv = Xb[(long)l0 * Dd];
        float mv = Mb[(long)l0 * Dd];
        float mx = xv * mv;
        #pragma unroll
        for (int hp = 0; hp < HP; hp++) {
            float w = wbuf[hp * 256 + l0];
            an[hp] = fmaf(w, mx, an[hp]);
            ad[hp] = fmaf(w, mv, ad[hp]);
        }
    }
    #pragma unroll
    for (int hp = 0; hp < HP; hp++) {
        g_pnum[((b * 8 + ch) * HP + hp) * Dd + c] = an[hp];
        g_pden[((b * 8 + ch) * HP + hp) * Dd + c] = ad[hp];
    }
}

// ---------------- kE: ratio -> coeffs -> d0,d1,d2   grid=(B,3), block=256
__global__ void kE(const float* __restrict__ W_o,
                   const float* __restrict__ W1,
                   const float* __restrict__ b1) {
    __shared__ float ratio[NH * Dd];   // 1024
    __shared__ float coef[LAT];
    int b = blockIdx.x, p = blockIdx.y;
    int tid = threadIdx.x;
    for (int i = tid; i < NH * Dd; i += 256) {
        int h = i >> 7, c = i & 127;
        int hp = h * 3 + p;
        float num = 0.f, den = 0.f;
        #pragma unroll
        for (int ch = 0; ch < 8; ch++) {
            num += g_pnum[((b * 8 + ch) * HP + hp) * Dd + c];
            den += g_pden[((b * 8 + ch) * HP + hp) * Dd + c];
        }
        ratio[i] = num / den;
    }
    __syncthreads();
    {
        int o = tid;
        float acc = g_boeff[o];
        for (int h = 0; h < NH; h++) {
            const float* wr = &W_o[(h * 2 * Dd) * LAT + o];
            const float* rr = &ratio[h * Dd];
            #pragma unroll 4
            for (int c = 0; c < Dd; c++)
                acc = fmaf(rr[c], wr[c * LAT], acc);
        }
        coef[o] = acc;
    }
    __syncthreads();
    for (int j = tid; j < HID; j += 256) {
        float acc = (p == 0) ? b1[j] : 0.f;
        #pragma unroll 4
        for (int o = 0; o < LAT; o++)
            acc = fmaf(coef[o], W1[o * HID + j], acc);
        g_d[(b * 3 + p) * HID + j] = acc;
    }
}

// ---------------- kF: fused h1 -> h2 -> out   grid=1024, block=256
// per block: 64 rows (one b). smem-tiled fp32 GEMM chain.
__global__ void kF(const float* __restrict__ yts,
                   const float* __restrict__ W2,
                   const float* __restrict__ b2,
                   const float* __restrict__ W3,
                   const float* __restrict__ b3,
                   float* __restrict__ out) {
    extern __shared__ float sm[];
    float* h1s  = sm;                    // 64*516
    float* w2t  = h1s + 64 * 516;        // 64*68
    float* h2c  = w2t + 64 * 68;         // 64*68
    float* w3t  = h2c + 64 * 68;         // 64*132
    float* dbuf = w3t + 64 * 132;        // 1536
    float* tvs  = dbuf + 1536;           // 64

    int tid = threadIdx.x;
    int bb = blockIdx.x >> 4;
    int t0 = (blockIdx.x & 15) * 64;

    for (int i = tid; i < 1536; i += 256) dbuf[i] = g_d[bb * 1536 + i];
    if (tid < 64) tvs[tid] = yts[bb * Tt + t0 + tid];
    __syncthreads();

    // h1 tile: relu(d0 + t*(d1 + t*d2))
    for (int i = tid; i < 64 * 512; i += 256) {
        int r = i >> 9, k = i & 511;
        float t = tvs[r];
        float v = fmaf(t, fmaf(t, dbuf[1024 + k], dbuf[512 + k]), dbuf[k]);
        h1s[r * 516 + k] = fmaxf(v, 0.f);
    }

    int tx = tid & 15, ty = tid >> 4;   // 16x16 thread grid
    float oacc[32];
    #pragma unroll
    for (int i = 0; i < 32; i++) oacc[i] = 0.f;

    for (int n0 = 0; n0 < 512; n0 += 64) {
        __syncthreads();    // h1s ready (first iter) / h2c,w3t reads done
        // stage W3 tile [64n x 128m]
        for (int i = tid; i < 64 * 32; i += 256) {
            int n = i >> 5, m4 = i & 31;
            *(float4*)&w3t[n * 132 + m4 * 4] =
                *(const float4*)&W3[(n0 + n) * 128 + m4 * 4];
        }
        float acc[16];
        #pragma unroll
        for (int i = 0; i < 16; i++) acc[i] = 0.f;

        for (int k0 = 0; k0 < 512; k0 += 64) {
            __syncthreads();    // w2t safe to overwrite (also orders w3t writes)
            for (int i = tid; i < 64 * 16; i += 256) {
                int k = i >> 4, n4 = i & 15;
                *(float4*)&w2t[k * 68 + n4 * 4] =
                    *(const float4*)&W2[(k0 + k) * 512 + n0 + n4 * 4];
            }
            __syncthreads();
            #pragma unroll 4
            for (int k = 0; k < 64; k++) {
                float a[4];
                #pragma unroll
                for (int i = 0; i < 4; i++)
                    a[i] = h1s[(ty * 4 + i) * 516 + k0 + k];
                float4 bv = *(const float4*)&w2t[k * 68 + tx * 4];
                #pragma unroll
                for (int i = 0; i < 4; i++) {
                    acc[i * 4 + 0] = fmaf(a[i], bv.x, acc[i * 4 + 0]);
                    acc[i * 4 + 1] = fmaf(a[i], bv.y, acc[i * 4 + 1]);
                    acc[i * 4 + 2] = fmaf(a[i], bv.z, acc[i * 4 + 2]);
                    acc[i * 4 + 3] = fmaf(a[i], bv.w, acc[i * 4 + 3]);
                }
            }
        }
        // relu(h2 + b2) chunk -> smem
        float b2v[4];
        #pragma unroll
        for (int j = 0; j < 4; j++) b2v[j] = b2[n0 + tx * 4 + j];
        #pragma unroll
        for (int i = 0; i < 4; i++)
            #pragma unroll
            for (int j = 0; j < 4; j++)
                h2c[(ty * 4 + i) * 68 + tx * 4 + j] =
                    fmaxf(acc[i * 4 + j] + b2v[j], 0.f);
        __syncthreads();
        // out += relu(h2) @ W3
        #pragma unroll 2
        for (int n = 0; n < 64; n++) {
            float a[4];
            #pragma unroll
            for (int i = 0; i < 4; i++)
                a[i] = h2c[(ty * 4 + i) * 68 + n];
            float4 q0 = *(const float4*)&w3t[n * 132 + tx * 8];
            float4 q1 = *(const float4*)&w3t[n * 132 + tx * 8 + 4];
            float wv[8] = {q0.x, q0.y, q0.z, q0.w, q1.x, q1.y, q1.z, q1.w};
            #pragma unroll
            for (int i = 0; i < 4; i++)
                #pragma unroll
                for (int j = 0; j < 8; j++)
                    oacc[i * 8 + j] = fmaf(a[i], wv[j], oacc[i * 8 + j]);
        }
    }
    // epilogue: + b3, store
    float b3v[8];
    #pragma unroll
    for (int j = 0; j < 8; j++) b3v[j] = b3[tx * 8 + j];
    #pragma unroll
    for (int i = 0; i < 4; i++) {
        long row = (long)bb * Tt + t0 + ty * 4 + i;
        float4 v0, v1;
        v0.x = oacc[i * 8 + 0] + b3v[0];
        v0.y = oacc[i * 8 + 1] + b3v[1];
        v0.z = oacc[i * 8 + 2] + b3v[2];
        v0.w = oacc[i * 8 + 3] + b3v[3];
        v1.x = oacc[i * 8 + 4] + b3v[4];
        v1.y = oacc[i * 8 + 5] + b3v[5];
        v1.z = oacc[i * 8 + 6] + b3v[6];
        v1.w = oacc[i * 8 + 7] + b3v[7];
        *(float4*)&out[row * 128 + tx * 8] = v0;
        *(float4*)&out[row * 128 + tx * 8 + 4] = v1;
    }
}

// ---------------------------------------------------------------------------
extern "C" void kernel_launch(void* const* d_in, const int* in_sizes, int n_in,
                              void* d_out, int out_size) {
    const float* timesteps = (const float*)d_in[0];
    const float* X         = (const float*)d_in[1];
    const float* M         = (const float*)d_in[2];
    const float* yts       = (const float*)d_in[3];
    const float* w_te      = (const float*)d_in[4];
    const float* b_te      = (const float*)d_in[5];
    const float* query     = (const float*)d_in[6];
    const float* W_q       = (const float*)d_in[7];
    const float* b_q       = (const float*)d_in[8];
    const float* W_k       = (const float*)d_in[9];
    const float* b_k       = (const float*)d_in[10];
    const float* W_o       = (const float*)d_in[11];
    const float* b_o       = (const float*)d_in[12];
    const float* W1        = (const float*)d_in[13];
    const float* b1        = (const float*)d_in[14];
    const float* W2        = (const float*)d_in[15];
    const float* b2        = (const float*)d_in[16];
    const float* W3        = (const float*)d_in[17];
    const float* b3        = (const float*)d_in[18];
    float* out = (float*)d_out;

    kA1<<<3, 512>>>(query, W_q, b_q);
    kA2<<<64, 256>>>(W_k);
    kA3<<<1, 256>>>(w_te, b_te, b_k, W_o, b_o);
    kB<<<512, 256>>>(timesteps, w_te, b_te);
    kC<<<Bb * HP, 128>>>();
    kD<<<dim3(Bb, 8), 128>>>(X, M);
    kE<<<dim3(Bb, 3), 256>>>(W_o, W1, b1);

    const int FSMEM = (64 * 516 + 64 * 68 + 64 * 68 + 64 * 132 + 1536 + 64) * 4;
    cudaFuncSetAttribute(kF, cudaFuncAttributeMaxDynamicSharedMemorySize, FSMEM);
    kF<<<1024, 256, FSMEM>>>(yts, W2, b2, W3, b3, out);
}

// round 3
// speedup vs baseline: 1.9264x; 1.9264x over previous
#include <cuda_runtime.h>
#include <cuda_bf16.h>
#include <cstdint>

// ---------------------------------------------------------------------------
// FLD fused forward.
//   Algebraic folding (unchanged from R1):
//     - W_k folded against batch-invariant q  -> 24-wide score projection
//     - key never materialized (affine in t + 64 sin terms)
//     - "ones" half of attention output folded into b_o_eff
//     - layer-1 GEMM folded through the polynomial in t (d0,d1,d2 per batch)
//   R2 (this submission, re-bench after broker timeout):
//     - kF rewritten on tensor cores: mma.sync m16n8k16 bf16, 3-term hi/lo
//       split (Ahi*Bhi + Ahi*Blo + Alo*Bhi) for ~fp32 accuracy.
//     - kW prep kernel pre-splits W2/W3 into transposed hi/lo bf16 planes.
// ---------------------------------------------------------------------------

#define Bb   64
#define Lq   2048
#define Tt   1024
#define Dd   128
#define Ee   512
#define NH   8
#define Pp   3
#define HP   24          // NH * Pp
#define LAT  256
#define HID  512

// scratch (static device allocations; no runtime alloc)
__device__ float g_q[Pp * Ee];            // q[p][e]
__device__ float g_A[Ee * HP];            // A[e][hp], hp = h*3+p, includes /8
__device__ float g_Clin[HP];
__device__ float g_Cconst[HP];
__device__ float g_boeff[LAT];
__device__ float g_scores[Bb * HP * Lq];  // [b][hp][l]
__device__ float g_rowmax[Bb * HP];
__device__ float g_pnum[Bb * 8 * HP * Dd];
__device__ float g_pden[Bb * 8 * HP * Dd];
__device__ float g_d[Bb * 3 * HID];       // d0,d1,d2 per batch

// bf16 hi/lo transposed weight planes (n-major: [n][k])
__device__ __nv_bfloat16 g_w2hiT[HID * HID];
__device__ __nv_bfloat16 g_w2loT[HID * HID];
__device__ __nv_bfloat16 g_w3hiT[Dd * HID];
__device__ __nv_bfloat16 g_w3loT[Dd * HID];

// ---------------- kA1: q[p][e] = query[p] @ W_q + b_q  (grid=3, block=512)
__global__ void kA1(const float* __restrict__ query,
                    const float* __restrict__ W_q,
                    const float* __restrict__ b_q) {
    int p = blockIdx.x;
    int e = threadIdx.x;
    float acc = b_q[e];
    for (int e2 = 0; e2 < Ee; e2++)
        acc = fmaf(query[p * Ee + e2], W_q[e2 * Ee + e], acc);
    g_q[p * Ee + e] = acc;
}

// ---------------- kA2: A[e][hp] = (1/8) sum_j W_k[e][h*64+j] * q[p][h*64+j]
__global__ void kA2(const float* __restrict__ W_k) {
    __shared__ float wk[8 * Ee];
    int tid = threadIdx.x;
    int e0 = blockIdx.x * 8;
    for (int i = tid; i < 8 * Ee / 4; i += 256)
        *(float4*)&wk[i * 4] = *(const float4*)&W_k[e0 * Ee + i * 4];
    __syncthreads();
    if (tid < 8 * HP) {
        int el = tid / HP;
        int hp = tid % HP;
        int h = hp / 3, p = hp % 3;
        const float* wr = &wk[el * Ee + h * 64];
        const float* qr = &g_q[p * Ee + h * 64];
        float acc = 0.f;
        #pragma unroll 8
        for (int j = 0; j < 64; j++)
            acc = fmaf(wr[j], qr[j], acc);
        g_A[(e0 + el) * HP + hp] = acc * 0.125f;
    }
}

// ---------------- kA3: C_lin, C_const (incl. bias from b_k), b_o_eff
__global__ void kA3(const float* __restrict__ w_te,
                    const float* __restrict__ b_te,
                    const float* __restrict__ b_k,
                    const float* __restrict__ W_o,
                    const float* __restrict__ b_o) {
    int tid = threadIdx.x;
    if (tid < HP) {
        int hp = tid;
        int h = hp / 3, p = hp % 3;
        float bias = 0.f;
        for (int j = 0; j < 64; j++)
            bias = fmaf(b_k[h * 64 + j], g_q[p * Ee + h * 64 + j], bias);
        bias *= 0.125f;
        float cl = 0.f, cc = 0.f;
        for (int e = 0; e < Ee; e++) {
            if ((e & 7) == 0) continue;
            float a = g_A[e * HP + hp];
            cl = fmaf(w_te[e], a, cl);
            cc = fmaf(b_te[e], a, cc);
        }
        g_Clin[hp] = cl;
        g_Cconst[hp] = cc + bias;
    }
    {
        int o = tid;
        float acc = b_o[o];
        for (int h = 0; h < NH; h++)
            for (int c = 0; c < Dd; c++)
                acc += W_o[(h * 2 * Dd + Dd + c) * LAT + o];
        g_boeff[o] = acc;
    }
}

// ---------------- kW: split + transpose W2, W3 into bf16 hi/lo planes
__global__ void kW(const float* __restrict__ W2,
                   const float* __restrict__ W3) {
    int idx = blockIdx.x * 256 + threadIdx.x;
    if (idx < HID * HID) {
        int k = idx >> 9, n = idx & 511;
        float v = W2[idx];
        __nv_bfloat16 hi = __float2bfloat16(v);
        __nv_bfloat16 lo = __float2bfloat16(v - __bfloat162float(hi));
        g_w2hiT[n * HID + k] = hi;
        g_w2loT[n * HID + k] = lo;
    } else {
        int i2 = idx - HID * HID;
        if (i2 < HID * Dd) {
            int k = i2 >> 7, n = i2 & 127;
            float v = W3[i2];
            __nv_bfloat16 hi = __float2bfloat16(v);
            __nv_bfloat16 lo = __float2bfloat16(v - __bfloat162float(hi));
            g_w3hiT[n * HID + k] = hi;
            g_w3loT[n * HID + k] = lo;
        }
    }
}

// ---------------- kB: scores[b][hp][l]   grid=512, block=256
__global__ void kB(const float* __restrict__ timesteps,
                   const float* __restrict__ w_te,
                   const float* __restrict__ b_te) {
    __shared__ float sAs[64 * HP];
    __shared__ float sw[64], sb[64], sCl[HP], sCc[HP];
    int tid = threadIdx.x;
    for (int i = tid; i < 64 * HP; i += 256) {
        int j = i / HP, hp = i % HP;
        sAs[i] = g_A[(j * 8) * HP + hp];
    }
    if (tid < 64) { sw[tid] = w_te[tid * 8]; sb[tid] = b_te[tid * 8]; }
    if (tid < HP) { sCl[tid] = g_Clin[tid]; sCc[tid] = g_Cconst[tid]; }
    __syncthreads();

    int idx = blockIdx.x * 256 + tid;
    float t = timesteps[idx];
    float acc[HP];
    #pragma unroll
    for (int hp = 0; hp < HP; hp++) acc[hp] = fmaf(t, sCl[hp], sCc[hp]);
    for (int j = 0; j < 64; j++) {
        float sv = sinf(fmaf(t, sw[j], sb[j]));
        #pragma unroll
        for (int hp = 0; hp < HP; hp++)
            acc[hp] = fmaf(sv, sAs[j * HP + hp], acc[hp]);
    }
    int b = idx >> 11, l = idx & 2047;
    #pragma unroll
    for (int hp = 0; hp < HP; hp++)
        g_scores[(b * HP + hp) * Lq + l] = acc[hp];
}

// ---------------- kC: row max over L   grid=B*HP, block=128
__global__ void kC() {
    int row = blockIdx.x;
    int tid = threadIdx.x;
    const float* s = &g_scores[row * Lq];
    float m = -1e30f;
    for (int l = tid; l < Lq; l += 128) m = fmaxf(m, s[l]);
    #pragma unroll
    for (int o = 16; o > 0; o >>= 1)
        m = fmaxf(m, __shfl_xor_sync(0xffffffffu, m, o));
    __shared__ float sm4[4];
    if ((tid & 31) == 0) sm4[tid >> 5] = m;
    __syncthreads();
    if (tid == 0)
        g_rowmax[row] = fmaxf(fmaxf(sm4[0], sm4[1]), fmaxf(sm4[2], sm4[3]));
}

// ---------------- kD: partial weighted sums   grid=(B,8), block=128
__global__ void kD(const float* __restrict__ X,
                   const float* __restrict__ M) {
    __shared__ float wbuf[HP * 256];
    __shared__ float srm[HP];
    int b = blockIdx.x, ch = blockIdx.y;
    int tid = threadIdx.x;
    if (tid < HP) srm[tid] = g_rowmax[b * HP + tid];
    __syncthreads();
    for (int i = tid; i < HP * 256; i += 128) {
        int hp = i >> 8, l0 = i & 255;
        wbuf[i] = expf(g_scores[(b * HP + hp) * Lq + ch * 256 + l0] - srm[hp]);
    }
    __syncthreads();

    float an[HP], ad[HP];
    #pragma unroll
    for (int hp = 0; hp < HP; hp++) { an[hp] = 0.f; ad[hp] = 0.f; }
    int c = tid;
    const float* Xb = X + ((long)b * Lq + ch * 256) * Dd + c;
    const float* Mb = M + ((long)b * Lq + ch * 256) * Dd + c;
    for (int l0 = 0; l0 < 256; l0++) {
        float xv = Xb[(long)l0 * Dd];
        float mv = Mb[(long)l0 * Dd];
        float mx = xv * mv;
        #pragma unroll
        for (int hp = 0; hp < HP; hp++) {
            float w = wbuf[hp * 256 + l0];
            an[hp] = fmaf(w, mx, an[hp]);
            ad[hp] = fmaf(w, mv, ad[hp]);
        }
    }
    #pragma unroll
    for (int hp = 0; hp < HP; hp++) {
        g_pnum[((b * 8 + ch) * HP + hp) * Dd + c] = an[hp];
        g_pden[((b * 8 + ch) * HP + hp) * Dd + c] = ad[hp];
    }
}

// ---------------- kE: ratio -> coeffs -> d0,d1,d2   grid=(B,3), block=256
__global__ void kE(const float* __restrict__ W_o,
                   const float* __restrict__ W1,
                   const float* __restrict__ b1) {
    __shared__ float ratio[NH * Dd];
    __shared__ float coef[LAT];
    int b = blockIdx.x, p = blockIdx.y;
    int tid = threadIdx.x;
    for (int i = tid; i < NH * Dd; i += 256) {
        int h = i >> 7, c = i & 127;
        int hp = h * 3 + p;
        float num = 0.f, den = 0.f;
        #pragma unroll
        for (int ch = 0; ch < 8; ch++) {
            num += g_pnum[((b * 8 + ch) * HP + hp) * Dd + c];
            den += g_pden[((b * 8 + ch) * HP + hp) * Dd + c];
        }
        ratio[i] = num / den;
    }
    __syncthreads();
    {
        int o = tid;
        float acc = g_boeff[o];
        for (int h = 0; h < NH; h++) {
            const float* wr = &W_o[(h * 2 * Dd) * LAT + o];
            const float* rr = &ratio[h * Dd];
            #pragma unroll 4
            for (int c = 0; c < Dd; c++)
                acc = fmaf(rr[c], wr[c * LAT], acc);
        }
        coef[o] = acc;
    }
    __syncthreads();
    for (int j = tid; j < HID; j += 256) {
        float acc = (p == 0) ? b1[j] : 0.f;
        #pragma unroll 4
        for (int o = 0; o < LAT; o++)
            acc = fmaf(coef[o], W1[o * HID + j], acc);
        g_d[(b * 3 + p) * HID + j] = acc;
    }
}

// ---------------- kF: fused h1 -> h2 -> out on tensor cores ----------------
// grid=1024 blocks (one per 64 output rows), block=256 (8 warps).
// GEMM1: h2 = relu(h1 @ W2 + b2), chunked over n0 (64 cols at a time).
// GEMM2: out += h2chunk @ W3chunk, accumulated across n0.
// 3-split bf16 mma per tile: Ahi*Bhi + Ahi*Blo + Alo*Bhi.

#define H1S 520   // h1 plane row stride (bf16): 520*2B -> banks 4g+tg distinct
#define SW  72    // stage / h2 row stride (bf16): 72*2B -> banks 4n+tg distinct

__device__ __forceinline__ void mma3(float* c,
    uint32_t a0, uint32_t a1, uint32_t a2, uint32_t a3,
    uint32_t b0, uint32_t b1) {
    asm volatile(
        "mma.sync.aligned.m16n8k16.row.col.f32.bf16.bf16.f32 "
        "{%0,%1,%2,%3}, {%4,%5,%6,%7}, {%8,%9}, {%0,%1,%2,%3};\n"
        : "+f"(c[0]), "+f"(c[1]), "+f"(c[2]), "+f"(c[3])
        : "r"(a0), "r"(a1), "r"(a2), "r"(a3), "r"(b0), "r"(b1));
}

__device__ __forceinline__ uint32_t ldb32(const __nv_bfloat16* p) {
    return *reinterpret_cast<const uint32_t*>(p);
}

__global__ void __launch_bounds__(256, 1)
kF(const float* __restrict__ yts,
   const float* __restrict__ b2,
   const float* __restrict__ b3,
   float* __restrict__ out) {
    extern __shared__ __align__(16) char smraw[];
    __nv_bfloat16* h1hi = (__nv_bfloat16*)smraw;            // 64*520
    __nv_bfloat16* h1lo = h1hi + 64 * H1S;                  // 64*520
    __nv_bfloat16* swbuf = h1lo + 64 * H1S;                 // 18432 (union)
    __nv_bfloat16* h2hi = swbuf + 128 * SW * 2;             // 64*72
    __nv_bfloat16* h2lo = h2hi + 64 * SW;                   // 64*72
    float* dbuf = (float*)(h2lo + 64 * SW);                 // 1536
    float* tvs  = dbuf + 1536;                              // 64

    int tid = threadIdx.x;
    int lane = tid & 31, warp = tid >> 5;
    int g = lane >> 2, tg = lane & 3;
    int wm = warp & 3, wn = warp >> 2;
    int bb = blockIdx.x >> 4;
    int t0 = (blockIdx.x & 15) * 64;

    for (int i = tid; i < 1536; i += 256) dbuf[i] = g_d[bb * 1536 + i];
    if (tid < 64) tvs[tid] = yts[bb * Tt + t0 + tid];
    __syncthreads();

    // h1 tile: relu(d0 + t*(d1 + t*d2)), split hi/lo
    for (int i = tid; i < 64 * 512; i += 256) {
        int r = i >> 9, k = i & 511;
        float t = tvs[r];
        float v = fmaf(t, fmaf(t, dbuf[1024 + k], dbuf[512 + k]), dbuf[k]);
        v = fmaxf(v, 0.f);
        __nv_bfloat16 hi = __float2bfloat16(v);
        h1hi[r * H1S + k] = hi;
        h1lo[r * H1S + k] = __float2bfloat16(v - __bfloat162float(hi));
    }

    float oacc[32];
    #pragma unroll
    for (int i = 0; i < 32; i++) oacc[i] = 0.f;

    const int SW2LO = 64 * SW;    // lo plane offset during GEMM1 staging
    const int SW3LO = 128 * SW;   // lo plane offset during GEMM2 staging

    for (int n0 = 0; n0 < HID; n0 += 64) {
        float acc1[16];
        #pragma unroll
        for (int i = 0; i < 16; i++) acc1[i] = 0.f;

        for (int k0 = 0; k0 < HID; k0 += 64) {
            __syncthreads();   // prior users of swbuf / h1 staging done
            // stage W2T chunk [64 n][64 k], hi+lo planes
            for (int i = tid; i < 512; i += 256) {
                int n = i >> 3, kq = i & 7;
                *(uint4*)&swbuf[n * SW + kq * 8] =
                    *(const uint4*)&g_w2hiT[(n0 + n) * HID + k0 + kq * 8];
                *(uint4*)&swbuf[SW2LO + n * SW + kq * 8] =
                    *(const uint4*)&g_w2loT[(n0 + n) * HID + k0 + kq * 8];
            }
            __syncthreads();
            #pragma unroll
            for (int ks = 0; ks < 4; ks++) {
                int k = k0 + ks * 16;
                const __nv_bfloat16* ah = &h1hi[(16 * wm + g) * H1S + k + 2 * tg];
                const __nv_bfloat16* al = &h1lo[(16 * wm + g) * H1S + k + 2 * tg];
                uint32_t a0 = ldb32(ah), a1 = ldb32(ah + 8 * H1S);
                uint32_t a2 = ldb32(ah + 8), a3 = ldb32(ah + 8 * H1S + 8);
                uint32_t l0 = ldb32(al), l1 = ldb32(al + 8 * H1S);
                uint32_t l2 = ldb32(al + 8), l3 = ldb32(al + 8 * H1S + 8);
                #pragma unroll
                for (int nt = 0; nt < 4; nt++) {
                    int n = 32 * wn + 8 * nt + g;
                    const __nv_bfloat16* bh = &swbuf[n * SW + ks * 16 + 2 * tg];
                    uint32_t b0 = ldb32(bh), b1 = ldb32(bh + 8);
                    uint32_t c0 = ldb32(bh + SW2LO), c1 = ldb32(bh + SW2LO + 8);
                    mma3(acc1 + nt * 4, a0, a1, a2, a3, b0, b1);
                    mma3(acc1 + nt * 4, a0, a1, a2, a3, c0, c1);
                    mma3(acc1 + nt * 4, l0, l1, l2, l3, b0, b1);
                }
            }
        }
        // h2 chunk: +b2, relu, split, -> smem planes
        {
            int r0 = 16 * wm + g;
            #pragma unroll
            for (int nt = 0; nt < 4; nt++) {
                int c = 32 * wn + 8 * nt + 2 * tg;
                float bv0 = b2[n0 + c], bv1 = b2[n0 + c + 1];
                float v00 = fmaxf(acc1[nt * 4 + 0] + bv0, 0.f);
                float v01 = fmaxf(acc1[nt * 4 + 1] + bv1, 0.f);
                float v10 = fmaxf(acc1[nt * 4 + 2] + bv0, 0.f);
                float v11 = fmaxf(acc1[nt * 4 + 3] + bv1, 0.f);
                __nv_bfloat16 h00 = __float2bfloat16(v00);
                __nv_bfloat16 h01 = __float2bfloat16(v01);
                __nv_bfloat16 h10 = __float2bfloat16(v10);
                __nv_bfloat16 h11 = __float2bfloat16(v11);
                h2hi[r0 * SW + c] = h00;
                h2hi[r0 * SW + c + 1] = h01;
                h2hi[(r0 + 8) * SW + c] = h10;
                h2hi[(r0 + 8) * SW + c + 1] = h11;
                h2lo[r0 * SW + c] = __float2bfloat16(v00 - __bfloat162float(h00));
                h2lo[r0 * SW + c + 1] = __float2bfloat16(v01 - __bfloat162float(h01));
                h2lo[(r0 + 8) * SW + c] = __float2bfloat16(v10 - __bfloat162float(h10));
                h2lo[(r0 + 8) * SW + c + 1] = __float2bfloat16(v11 - __bfloat162float(h11));
            }
        }
        __syncthreads();   // all GEMM1 swbuf reads done; h2 writes done
        // stage W3T chunk [128 n][64 k] (k = n0..n0+64), hi+lo planes
        for (int i = tid; i < 1024; i += 256) {
            int n = i >> 3, kq = i & 7;
            *(uint4*)&swbuf[n * SW + kq * 8] =
                *(const uint4*)&g_w3hiT[n * HID + n0 + kq * 8];
            *(uint4*)&swbuf[SW3LO + n * SW + kq * 8] =
                *(const uint4*)&g_w3loT[n * HID + n0 + kq * 8];
        }
        __syncthreads();
        // GEMM2: out[64x128] += h2chunk[64x64] @ W3chunk[64x128]
        #pragma unroll
        for (int ks = 0; ks < 4; ks++) {
            int kk = ks * 16;
            const __nv_bfloat16* ah = &h2hi[(16 * wm + g) * SW + kk + 2 * tg];
            const __nv_bfloat16* al = &h2lo[(16 * wm + g) * SW + kk + 2 * tg];
            uint32_t a0 = ldb32(ah), a1 = ldb32(ah + 8 * SW);
            uint32_t a2 = ldb32(ah + 8), a3 = ldb32(ah + 8 * SW + 8);
            uint32_t l0 = ldb32(al), l1 = ldb32(al + 8 * SW);
            uint32_t l2 = ldb32(al + 8), l3 = ldb32(al + 8 * SW + 8);
            #pragma unroll
            for (int nt = 0; nt < 8; nt++) {
                int n = 64 * wn + 8 * nt + g;
                const __nv_bfloat16* bh = &swbuf[n * SW + kk + 2 * tg];
                uint32_t b0 = ldb32(bh), b1 = ldb32(bh + 8);
                uint32_t c0 = ldb32(bh + SW3LO), c1 = ldb32(bh + SW3LO + 8);
                mma3(oacc + nt * 4, a0, a1, a2, a3, b0, b1);
                mma3(oacc + nt * 4, a0, a1, a2, a3, c0, c1);
                mma3(oacc + nt * 4, l0, l1, l2, l3, b0, b1);
            }
        }
    }
    // epilogue: +b3, store
    {
        long row0 = (long)bb * Tt + t0 + 16 * wm + g;
        #pragma unroll
        for (int nt = 0; nt < 8; nt++) {
            int col = 64 * wn + 8 * nt + 2 * tg;
            float bv0 = b3[col], bv1 = b3[col + 1];
            float2 s0 = {oacc[nt * 4 + 0] + bv0, oacc[nt * 4 + 1] + bv1};
            float2 s1 = {oacc[nt * 4 + 2] + bv0, oacc[nt * 4 + 3] + bv1};
            *(float2*)&out[row0 * 128 + col] = s0;
            *(float2*)&out[(row0 + 8) * 128 + col] = s1;
        }
    }
}

// ---------------------------------------------------------------------------
extern "C" void kernel_launch(void* const* d_in, const int* in_sizes, int n_in,
                              void* d_out, int out_size) {
    const float* timesteps = (const float*)d_in[0];
    const float* X         = (const float*)d_in[1];
    const float* M         = (const float*)d_in[2];
    const float* yts       = (const float*)d_in[3];
    const float* w_te      = (const float*)d_in[4];
    const float* b_te      = (const float*)d_in[5];
    const float* query     = (const float*)d_in[6];
    const float* W_q       = (const float*)d_in[7];
    const float* b_q       = (const float*)d_in[8];
    const float* W_k       = (const float*)d_in[9];
    const float* b_k       = (const float*)d_in[10];
    const float* W_o       = (const float*)d_in[11];
    const float* b_o       = (const float*)d_in[12];
    const float* W1        = (const float*)d_in[13];
    const float* b1        = (const float*)d_in[14];
    const float* W2        = (const float*)d_in[15];
    const float* b2        = (const float*)d_in[16];
    const float* W3        = (const float*)d_in[17];
    const float* b3        = (const float*)d_in[18];
    float* out = (float*)d_out;

    kW<<<1280, 256>>>(W2, W3);
    kA1<<<3, 512>>>(query, W_q, b_q);
    kA2<<<64, 256>>>(W_k);
    kA3<<<1, 256>>>(w_te, b_te, b_k, W_o, b_o);
    kB<<<512, 256>>>(timesteps, w_te, b_te);
    kC<<<Bb * HP, 128>>>();
    kD<<<dim3(Bb, 8), 128>>>(X, M);
    kE<<<dim3(Bb, 3), 256>>>(W_o, W1, b1);

    const int FSMEM =
        (2 * 64 * H1S + 2 * 128 * SW + 2 * 64 * SW) * 2 + (1536 + 64) * 4;
    cudaFuncSetAttribute(kF, cudaFuncAttributeMaxDynamicSharedMemorySize, FSMEM);
    kF<<<1024, 256, FSMEM>>>(yts, b2, b3, out);
}